// round 6
// baseline (speedup 1.0000x reference)
#include <cuda_runtime.h>

#define NANCH 19200      // 3*80*80 anchors per image
#define NIMG  8
#define MTGT  100
#define HALFM 50
#define NCLS  80
#define THREADS 128
#define NWARP (THREADS / 32)
#define APB 64                              // anchors per block (2 threads/anchor)
#define NBLK_PER_IMG (NANCH / APB)          // 300
#define NBLOCKS (NIMG * NBLK_PER_IMG)       // 2400

__device__ float    g_part[NBLOCKS * 4];
__device__ unsigned g_count;

__device__ __forceinline__ float frcp_approx(float x) {
    float r;
    asm("rcp.approx.f32 %0, %1;" : "=f"(r) : "f"(x));
    return r;
}

__global__ void __launch_bounds__(THREADS) loss_fused(
    const float* __restrict__ obj,    // [8,19200]
    const float* __restrict__ boxes,  // [8,19200,4] (cx,cy,w,h)
    const float* __restrict__ cls,    // [8,19200,80]
    const float* __restrict__ tbox,   // [8,100,4]
    const int*   __restrict__ tlab,   // [8,100]
    float*       __restrict__ out)
{
    __shared__ float4 s_lohi[MTGT];          // lox,loy,hix,hiy
    __shared__ float  s_area[MTGT];
    __shared__ int    s_lab[MTGT];
    __shared__ int    s_vm[THREADS];         // packed argmax halves
    __shared__ int    s_pos_row[APB];
    __shared__ int    s_pos_lab[APB];
    __shared__ int    s_pos_tgt[APB];
    __shared__ int    s_wtot[NWARP];
    __shared__ float  s_red[NWARP];
    __shared__ float  s_img[NIMG][4];
    __shared__ unsigned s_is_last;

    const int tid  = threadIdx.x;
    const int lane = tid & 31;
    const int wid  = tid >> 5;
    const int img  = blockIdx.x / NBLK_PER_IMG;
    const int ablk = blockIdx.x % NBLK_PER_IMG;
    const int aloc = tid & (APB - 1);              // anchor slot 0..63
    const int half = tid >> 6;                     // 0: targets [0,50), 1: [50,100)
    const int row  = img * NANCH + ablk * APB + aloc;

    // ── Targets to shared ──
    if (tid < MTGT) {
        float4 tb = ((const float4*)tbox)[img * MTGT + tid];
        s_lohi[tid] = make_float4(tb.x - 0.5f * tb.z, tb.y - 0.5f * tb.w,
                                  tb.x + 0.5f * tb.z, tb.y + 0.5f * tb.w);
        s_area[tid] = tb.z * tb.w;
        s_lab[tid]  = tlab[img * MTGT + tid];
    }
    __syncthreads();

    // ── Anchor box (both halves load the same anchor) ──
    float4 bx = ((const float4*)boxes)[row];
    const float lo1x = bx.x - 0.5f * bx.z, lo1y = bx.y - 0.5f * bx.w;
    const float hi1x = bx.x + 0.5f * bx.z, hi1y = bx.y + 0.5f * bx.w;
    const float a1   = bx.z * bx.w;

    // ── Packed argmax of x = inter/(a1+ta) over this thread's 50 targets.
    //    idx in low 7 mantissa bits (127-m): IMAX picks larger x, tie -> lower m.
    int vmax = (int)0x80000000;
    const int m0 = half * HALFM;
    #pragma unroll 5
    for (int k = 0; k < HALFM; k++) {
        int m = m0 + k;
        float4 t  = s_lohi[m];
        float  ta = s_area[m];
        float wx = fminf(hi1x, t.z) - fmaxf(lo1x, t.x);             // unclamped
        float wy = fmaxf(fminf(hi1y, t.w) - fmaxf(lo1y, t.y), 0.0f);
        float inter = wx * wy;
        float x  = inter * frcp_approx(a1 + ta);
        int pk = (__float_as_int(x) & (int)0xFFFFFF80) | (127 - m);
        vmax = max(vmax, pk);
    }
    s_vm[tid] = vmax;
    __syncthreads();

    // ── Per-anchor results on threads 0..63 ──
    bool  pos = false;
    float bce = 0.0f, posf = 0.0f;
    int   bidx = 0;
    if (tid < APB) {
        int v = max(s_vm[tid], s_vm[tid + APB]);
        bidx = 127 - (v & 127);
        // exact positivity on winner: iou>=0.5 <=> 3*inter >= a1+ta+1e-6
        float4 t = s_lohi[bidx];
        float wx = fmaxf(fminf(hi1x, t.z) - fmaxf(lo1x, t.x), 0.0f);
        float wy = fmaxf(fminf(hi1y, t.w) - fmaxf(lo1y, t.y), 0.0f);
        pos = (3.0f * (wx * wy) >= a1 + s_area[bidx] + 1e-6f);
        posf = pos ? 1.0f : 0.0f;
        float o = obj[row];
        bce = -fmaxf(__logf(pos ? o : 1.0f - o), -100.0f);
    }

    // ── Deterministic compaction of positives ──
    unsigned ball = __ballot_sync(0xFFFFFFFFu, pos);
    if (lane == 0) s_wtot[wid] = __popc(ball);
    __syncthreads();
    int wbase = 0, P = 0;
    #pragma unroll
    for (int w = 0; w < NWARP; w++) {
        wbase += (w < wid) ? s_wtot[w] : 0;
        P += s_wtot[w];
    }
    if (pos) {
        int ofs = wbase + __popc(ball & ((1u << lane) - 1u));
        s_pos_row[ofs] = row;
        s_pos_tgt[ofs] = bidx;
        s_pos_lab[ofs] = s_lab[bidx];
    }
    __syncthreads();

    // ── GIoU for positives, strided (deterministic) ──
    float bbox = 0.0f;
    for (int i = tid; i < P; i += THREADS) {
        float4 pb = ((const float4*)boxes)[s_pos_row[i]];   // L1-hot
        float plox = pb.x - 0.5f * pb.z, ploy = pb.y - 0.5f * pb.w;
        float phix = pb.x + 0.5f * pb.z, phiy = pb.y + 0.5f * pb.w;
        float pa   = pb.z * pb.w;
        int   bm   = s_pos_tgt[i];
        float4 t = s_lohi[bm];
        float wx = fmaxf(fminf(phix, t.z) - fmaxf(plox, t.x), 0.0f);
        float wy = fmaxf(fminf(phiy, t.w) - fmaxf(ploy, t.y), 0.0f);
        float inter = wx * wy;
        float uni = pa + s_area[bm] - inter;
        float iou = __fdividef(inter, uni + 1e-6f);
        float ex = fmaxf(fmaxf(phix, t.z) - fminf(plox, t.x), 0.0f);
        float ey = fmaxf(fmaxf(phiy, t.w) - fminf(ploy, t.y), 0.0f);
        float enc = ex * ey;
        bbox += 1.0f - (iou - __fdividef(enc - uni, enc + 1e-6f));
    }

    // ── Focal loss over positives (P*80 items, incremental indexing) ──
    float fl = 0.0f;
    {
        const int items = P * NCLS;
        int a = 0, c = tid;
        if (c >= NCLS) { c -= NCLS; a += 1; }
        for (int i = tid; i < items; i += THREADS) {
            float x = cls[s_pos_row[a] * NCLS + c];
            bool t = (c == s_pos_lab[a]);
            float e  = __expf(-fabsf(x));
            float q  = 1.0f + e;
            float pabs = frcp_approx(q);               // sigmoid(|x|) approx
            float lg = __logf(q);                      // log1p(exp(-|x|))
            float p  = (x >= 0.0f) ? pabs : 1.0f - pabs;
            float omp = t ? (1.0f - p) : p;            // 1 - p_t
            float ce = lg + fmaxf(t ? -x : x, 0.0f);
            float at = t ? 0.25f : 0.75f;
            fl += at * omp * omp * ce;
            c += THREADS - NCLS;                       // +48
            a += 1;
            if (c >= NCLS) { c -= NCLS; a += 1; }
        }
    }

    // ── block reduction of (bce, posf, bbox, fl) — deterministic ──
    float vals[4] = {bce, posf, bbox, fl};
    #pragma unroll
    for (int k = 0; k < 4; k++) {
        float v = vals[k];
        #pragma unroll
        for (int off = 16; off > 0; off >>= 1)
            v += __shfl_down_sync(0xFFFFFFFFu, v, off);
        if (lane == 0) s_red[wid] = v;
        __syncthreads();
        if (tid == 0) {
            float r = 0.0f;
            #pragma unroll
            for (int w = 0; w < NWARP; w++) r += s_red[w];
            g_part[blockIdx.x * 4 + k] = r;
        }
        __syncthreads();
    }

    // ── last-block finalize ──
    __threadfence();
    if (tid == 0) s_is_last = (atomicAdd(&g_count, 1) == NBLOCKS - 1) ? 1u : 0u;
    __syncthreads();
    if (!s_is_last) return;
    __threadfence();

    {
        int fimg = tid >> 4;        // 0..7 (128 threads = 8 imgs x 16 slots)
        int sub  = tid & 15;        // 0..15
        float v0 = 0, v1 = 0, v2 = 0, v3 = 0;
        for (int s = sub; s < NBLK_PER_IMG; s += 16) {
            int b = fimg * NBLK_PER_IMG + s;
            v0 += g_part[b * 4 + 0];
            v1 += g_part[b * 4 + 1];
            v2 += g_part[b * 4 + 2];
            v3 += g_part[b * 4 + 3];
        }
        #pragma unroll
        for (int off = 8; off > 0; off >>= 1) {
            v0 += __shfl_down_sync(0xFFFFFFFFu, v0, off, 16);
            v1 += __shfl_down_sync(0xFFFFFFFFu, v1, off, 16);
            v2 += __shfl_down_sync(0xFFFFFFFFu, v2, off, 16);
            v3 += __shfl_down_sync(0xFFFFFFFFu, v3, off, 16);
        }
        if (sub == 0) {
            s_img[fimg][0] = v0; s_img[fimg][1] = v1;
            s_img[fimg][2] = v2; s_img[fimg][3] = v3;
        }
        __syncthreads();
        if (tid == 0) {
            float obj_sum = 0, bbox_sum = 0, cls_sum = 0, num_pos = 0;
            #pragma unroll
            for (int i = 0; i < NIMG; i++) {
                float bces = s_img[i][0];
                float pc   = s_img[i][1];
                float bb   = s_img[i][2];
                float fls  = s_img[i][3];
                obj_sum  += bces * (1.0f * pc + 0.5f * ((float)NANCH - pc));
                bbox_sum += bb;
                cls_sum  += fls / fmaxf(pc * (float)NCLS, 1.0f);
                num_pos  += pc;
            }
            num_pos = fmaxf(num_pos, 1.0f);
            out[0] = obj_sum / (float)NIMG
                   + 5.0f * bbox_sum / num_pos
                   + cls_sum / (float)NIMG;
            g_count = 0;   // reset for next graph replay
        }
    }
}

extern "C" void kernel_launch(void* const* d_in, const int* in_sizes, int n_in,
                              void* d_out, int out_size) {
    const float* obj   = (const float*)d_in[0];
    const float* boxes = (const float*)d_in[1];
    const float* cls   = (const float*)d_in[2];
    const float* tbox  = (const float*)d_in[3];
    const int*   tlab  = (const int*)d_in[4];
    float* out = (float*)d_out;

    loss_fused<<<NBLOCKS, THREADS>>>(obj, boxes, cls, tbox, tlab, out);
}

// round 7
// speedup vs baseline: 1.2017x; 1.2017x over previous
#include <cuda_runtime.h>

#define NANCH 19200      // 3*80*80 anchors per image
#define NIMG  8
#define MTGT  100
#define NCLS  80
#define THREADS 256
#define NWARP (THREADS / 32)
#define ANCH_PER_BLK THREADS                // 256, 1 anchor/thread
#define NBLK_PER_IMG (NANCH / ANCH_PER_BLK) // 75
#define NBLOCKS (NIMG * NBLK_PER_IMG)       // 600

__device__ float    g_part[NBLOCKS * 4];
__device__ unsigned g_count;

__device__ __forceinline__ float frcp_approx(float x) {
    float r;
    asm("rcp.approx.f32 %0, %1;" : "=f"(r) : "f"(x));
    return r;
}

__global__ void __launch_bounds__(THREADS) loss_fused(
    const float* __restrict__ obj,    // [8,19200]
    const float* __restrict__ boxes,  // [8,19200,4] (cx,cy,w,h)
    const float* __restrict__ cls,    // [8,19200,80]
    const float* __restrict__ tbox,   // [8,100,4]
    const int*   __restrict__ tlab,   // [8,100]
    float*       __restrict__ out)
{
    __shared__ float4 s_lohi[MTGT];          // lox,loy,hix,hiy
    __shared__ float  s_area[MTGT];
    __shared__ int    s_lab[MTGT];
    __shared__ int    s_pos_row[THREADS];
    __shared__ int    s_pos_lab[THREADS];
    __shared__ int    s_pos_tgt[THREADS];
    __shared__ int    s_wtot[NWARP];
    __shared__ float  s_red[NWARP];
    __shared__ float  s_img[NIMG][4];
    __shared__ unsigned s_is_last;

    const int tid  = threadIdx.x;
    const int lane = tid & 31;
    const int wid  = tid >> 5;
    const int img  = blockIdx.x / NBLK_PER_IMG;
    const int ablk = blockIdx.x % NBLK_PER_IMG;
    const int row  = img * NANCH + ablk * ANCH_PER_BLK + tid;

    // ── Targets to shared (256 threads cover 100 targets in one pass) ──
    if (tid < MTGT) {
        float4 tb = ((const float4*)tbox)[img * MTGT + tid];
        s_lohi[tid] = make_float4(tb.x - 0.5f * tb.z, tb.y - 0.5f * tb.w,
                                  tb.x + 0.5f * tb.z, tb.y + 0.5f * tb.w);
        s_area[tid] = tb.z * tb.w;
        s_lab[tid]  = tlab[img * MTGT + tid];
    }
    __syncthreads();

    // ── Anchor box ──
    float4 bx = ((const float4*)boxes)[row];
    const float lo1x = bx.x - 0.5f * bx.z, lo1y = bx.y - 0.5f * bx.w;
    const float hi1x = bx.x + 0.5f * bx.z, hi1y = bx.y + 0.5f * bx.w;
    const float a1   = bx.z * bx.w;

    // ── Packed argmax of x = inter/(a1+ta)  (monotone in IoU).
    //    Index in low 7 mantissa bits (127-m): IMAX -> larger x, tie -> lower m.
    int vmax = (int)0x80000000;
    #pragma unroll 5
    for (int m = 0; m < MTGT; m++) {
        float4 t  = s_lohi[m];
        float  ta = s_area[m];
        float wx = fminf(hi1x, t.z) - fmaxf(lo1x, t.x);              // unclamped
        float wy = fmaxf(fminf(hi1y, t.w) - fmaxf(lo1y, t.y), 0.0f);
        float inter = wx * wy;
        float x  = inter * frcp_approx(a1 + ta);
        int pk = (__float_as_int(x) & (int)0xFFFFFF80) | (127 - m);
        vmax = max(vmax, pk);
    }
    const int bidx = 127 - (vmax & 127);

    // exact positivity confirm on winner: iou>=0.5 <=> 3*inter >= a1+ta+1e-6
    bool pos;
    {
        float4 t = s_lohi[bidx];
        float wx = fmaxf(fminf(hi1x, t.z) - fmaxf(lo1x, t.x), 0.0f);
        float wy = fmaxf(fminf(hi1y, t.w) - fmaxf(lo1y, t.y), 0.0f);
        pos = (3.0f * (wx * wy) >= a1 + s_area[bidx] + 1e-6f);
    }
    const float posf = pos ? 1.0f : 0.0f;

    // ── Objectness BCE ──
    float o = obj[row];
    float bce = -fmaxf(__logf(pos ? o : 1.0f - o), -100.0f);

    // ── Deterministic compaction of positives ──
    unsigned ball = __ballot_sync(0xFFFFFFFFu, pos);
    if (lane == 0) s_wtot[wid] = __popc(ball);
    __syncthreads();
    int wbase = 0, P = 0;
    #pragma unroll
    for (int w = 0; w < NWARP; w++) {
        wbase += (w < wid) ? s_wtot[w] : 0;
        P += s_wtot[w];
    }
    if (pos) {
        int ofs = wbase + __popc(ball & ((1u << lane) - 1u));
        s_pos_row[ofs] = row;
        s_pos_tgt[ofs] = bidx;
        s_pos_lab[ofs] = s_lab[bidx];
    }
    __syncthreads();

    // ── GIoU for positives, strided (deterministic) ──
    float bbox = 0.0f;
    for (int i = tid; i < P; i += THREADS) {
        float4 pb = ((const float4*)boxes)[s_pos_row[i]];   // L1-hot
        float plox = pb.x - 0.5f * pb.z, ploy = pb.y - 0.5f * pb.w;
        float phix = pb.x + 0.5f * pb.z, phiy = pb.y + 0.5f * pb.w;
        float pa   = pb.z * pb.w;
        int   bm   = s_pos_tgt[i];
        float4 t = s_lohi[bm];
        float wx = fmaxf(fminf(phix, t.z) - fmaxf(plox, t.x), 0.0f);
        float wy = fmaxf(fminf(phiy, t.w) - fmaxf(ploy, t.y), 0.0f);
        float inter = wx * wy;
        float uni = pa + s_area[bm] - inter;
        float iou = __fdividef(inter, uni + 1e-6f);
        float ex = fmaxf(fmaxf(phix, t.z) - fminf(plox, t.x), 0.0f);
        float ey = fmaxf(fmaxf(phiy, t.w) - fminf(ploy, t.y), 0.0f);
        float enc = ex * ey;
        bbox += 1.0f - (iou - __fdividef(enc - uni, enc + 1e-6f));
    }

    // ── Focal loss over positives (P*80 items, incremental indexing) ──
    float fl = 0.0f;
    {
        const int items = P * NCLS;
        int a = 0, c = tid;
        while (c >= NCLS) { c -= NCLS; a += 1; }      // 256/80: a in {0,1,2,3}
        for (int i = tid; i < items; i += THREADS) {
            float x = cls[s_pos_row[a] * NCLS + c];
            bool t = (c == s_pos_lab[a]);
            float e  = __expf(-fabsf(x));
            float q  = 1.0f + e;
            float pabs = frcp_approx(q);               // sigmoid(|x|)
            float lg = __logf(q);                      // log1p(exp(-|x|))
            float p  = (x >= 0.0f) ? pabs : 1.0f - pabs;
            float omp = t ? (1.0f - p) : p;            // 1 - p_t
            float ce = lg + fmaxf(t ? -x : x, 0.0f);
            float at = t ? 0.25f : 0.75f;
            fl += at * omp * omp * ce;
            c += THREADS - 3 * NCLS;                   // +16
            a += 3;
            if (c >= NCLS) { c -= NCLS; a += 1; }
        }
    }

    // ── block reduction of (bce, posf, bbox, fl) — deterministic ──
    float vals[4] = {bce, posf, bbox, fl};
    #pragma unroll
    for (int k = 0; k < 4; k++) {
        float v = vals[k];
        #pragma unroll
        for (int off = 16; off > 0; off >>= 1)
            v += __shfl_down_sync(0xFFFFFFFFu, v, off);
        if (lane == 0) s_red[wid] = v;
        __syncthreads();
        if (tid == 0) {
            float r = 0.0f;
            #pragma unroll
            for (int w = 0; w < NWARP; w++) r += s_red[w];
            g_part[blockIdx.x * 4 + k] = r;
        }
        __syncthreads();
    }

    // ── last-block finalize ──
    __threadfence();
    if (tid == 0) s_is_last = (atomicAdd(&g_count, 1) == NBLOCKS - 1) ? 1u : 0u;
    __syncthreads();
    if (!s_is_last) return;
    __threadfence();

    {
        int fimg = tid >> 5;        // 0..7 (256 threads = 8 imgs x 32 slots)
        int sub  = tid & 31;        // 0..31
        float v0 = 0, v1 = 0, v2 = 0, v3 = 0;
        for (int s = sub; s < NBLK_PER_IMG; s += 32) {
            int b = fimg * NBLK_PER_IMG + s;
            v0 += g_part[b * 4 + 0];
            v1 += g_part[b * 4 + 1];
            v2 += g_part[b * 4 + 2];
            v3 += g_part[b * 4 + 3];
        }
        #pragma unroll
        for (int off = 16; off > 0; off >>= 1) {
            v0 += __shfl_down_sync(0xFFFFFFFFu, v0, off);
            v1 += __shfl_down_sync(0xFFFFFFFFu, v1, off);
            v2 += __shfl_down_sync(0xFFFFFFFFu, v2, off);
            v3 += __shfl_down_sync(0xFFFFFFFFu, v3, off);
        }
        if (sub == 0) {
            s_img[fimg][0] = v0; s_img[fimg][1] = v1;
            s_img[fimg][2] = v2; s_img[fimg][3] = v3;
        }
        __syncthreads();
        if (tid == 0) {
            float obj_sum = 0, bbox_sum = 0, cls_sum = 0, num_pos = 0;
            #pragma unroll
            for (int i = 0; i < NIMG; i++) {
                float bces = s_img[i][0];
                float pc   = s_img[i][1];
                float bb   = s_img[i][2];
                float fls  = s_img[i][3];
                obj_sum  += bces * (1.0f * pc + 0.5f * ((float)NANCH - pc));
                bbox_sum += bb;
                cls_sum  += fls / fmaxf(pc * (float)NCLS, 1.0f);
                num_pos  += pc;
            }
            num_pos = fmaxf(num_pos, 1.0f);
            out[0] = obj_sum / (float)NIMG
                   + 5.0f * bbox_sum / num_pos
                   + cls_sum / (float)NIMG;
            g_count = 0;   // reset for next graph replay
        }
    }
}

extern "C" void kernel_launch(void* const* d_in, const int* in_sizes, int n_in,
                              void* d_out, int out_size) {
    const float* obj   = (const float*)d_in[0];
    const float* boxes = (const float*)d_in[1];
    const float* cls   = (const float*)d_in[2];
    const float* tbox  = (const float*)d_in[3];
    const int*   tlab  = (const int*)d_in[4];
    float* out = (float*)d_out;

    loss_fused<<<NBLOCKS, THREADS>>>(obj, boxes, cls, tbox, tlab, out);
}

// round 8
// speedup vs baseline: 1.2031x; 1.0012x over previous
#include <cuda_runtime.h>

#define NANCH 19200      // 3*80*80 anchors per image
#define NIMG  8
#define MTGT  100
#define NCLS  80
#define THREADS 128
#define NWARP (THREADS / 32)
#define APT 2                               // anchors per thread
#define ANCH_PER_BLK (THREADS * APT)        // 256
#define NBLK_PER_IMG (NANCH / ANCH_PER_BLK) // 75
#define NBLOCKS (NIMG * NBLK_PER_IMG)       // 600

__device__ float    g_part[NBLOCKS * 4];
__device__ unsigned g_count;

__device__ __forceinline__ float frcp_approx(float x) {
    float r;
    asm("rcp.approx.f32 %0, %1;" : "=f"(r) : "f"(x));
    return r;
}

__global__ void __launch_bounds__(THREADS) loss_fused(
    const float* __restrict__ obj,    // [8,19200]
    const float* __restrict__ boxes,  // [8,19200,4] (cx,cy,w,h)
    const float* __restrict__ cls,    // [8,19200,80]
    const float* __restrict__ tbox,   // [8,100,4]
    const int*   __restrict__ tlab,   // [8,100]
    float*       __restrict__ out)
{
    __shared__ float4 s_lohi[MTGT];          // lox,loy,hix,hiy
    __shared__ float  s_area[MTGT];
    __shared__ int    s_lab[MTGT];
    __shared__ int    s_pos_row[ANCH_PER_BLK];
    __shared__ int    s_pos_lab[ANCH_PER_BLK];
    __shared__ int    s_pos_tgt[ANCH_PER_BLK];
    __shared__ int    s_wtot[NWARP];
    __shared__ float  s_red[NWARP][4];
    __shared__ float  s_img[NIMG][4];
    __shared__ unsigned s_is_last;

    const int tid  = threadIdx.x;
    const int lane = tid & 31;
    const int wid  = tid >> 5;
    const int img  = blockIdx.x / NBLK_PER_IMG;
    const int ablk = blockIdx.x % NBLK_PER_IMG;
    const int base = img * NANCH + ablk * ANCH_PER_BLK + tid * APT;

    // ── Targets to shared (128 threads cover 100 targets) ──
    if (tid < MTGT) {
        float4 tb = ((const float4*)tbox)[img * MTGT + tid];
        s_lohi[tid] = make_float4(tb.x - 0.5f * tb.z, tb.y - 0.5f * tb.w,
                                  tb.x + 0.5f * tb.z, tb.y + 0.5f * tb.w);
        s_area[tid] = tb.z * tb.w;
        s_lab[tid]  = tlab[img * MTGT + tid];
    }
    __syncthreads();

    // ── Load 2 anchor boxes ──
    float lo1x[APT], lo1y[APT], hi1x[APT], hi1y[APT], a1[APT];
    int   vmax[APT];
    #pragma unroll
    for (int a = 0; a < APT; a++) {
        float4 bxv = ((const float4*)boxes)[base + a];
        lo1x[a] = bxv.x - 0.5f * bxv.z;  lo1y[a] = bxv.y - 0.5f * bxv.w;
        hi1x[a] = bxv.x + 0.5f * bxv.z;  hi1y[a] = bxv.y + 0.5f * bxv.w;
        a1[a]   = bxv.z * bxv.w;
        vmax[a] = (int)0x80000000;
    }

    // ── Packed argmax of x = inter/(a1+ta) (monotone in IoU).
    //    One target fetch serves both anchors. Two independent IMAX chains.
    #pragma unroll 4
    for (int m = 0; m < MTGT; m++) {
        float4 t  = s_lohi[m];
        float  ta = s_area[m];
        int idxbits = 127 - m;
        #pragma unroll
        for (int a = 0; a < APT; a++) {
            float wx = fminf(hi1x[a], t.z) - fmaxf(lo1x[a], t.x);    // unclamped
            float wy = fmaxf(fminf(hi1y[a], t.w) - fmaxf(lo1y[a], t.y), 0.0f);
            float inter = wx * wy;
            float x  = inter * frcp_approx(a1[a] + ta);
            int pk = (__float_as_int(x) & (int)0xFFFFFF80) | idxbits;
            vmax[a] = max(vmax[a], pk);
        }
    }

    // ── per-anchor winner, exact positivity, BCE ──
    bool  pos[APT];
    int   bidx[APT];
    float bce = 0.0f, posf = 0.0f;
    #pragma unroll
    for (int a = 0; a < APT; a++) {
        bidx[a] = 127 - (vmax[a] & 127);
        float4 t = s_lohi[bidx[a]];
        float wx = fmaxf(fminf(hi1x[a], t.z) - fmaxf(lo1x[a], t.x), 0.0f);
        float wy = fmaxf(fminf(hi1y[a], t.w) - fmaxf(lo1y[a], t.y), 0.0f);
        pos[a] = (3.0f * (wx * wy) >= a1[a] + s_area[bidx[a]] + 1e-6f);
        posf += pos[a] ? 1.0f : 0.0f;
        float o = obj[base + a];
        bce += -fmaxf(__logf(pos[a] ? o : 1.0f - o), -100.0f);
    }

    // ── deterministic compaction of positives (anchor order) ──
    int c = (pos[0] ? 1 : 0) + (pos[1] ? 1 : 0);
    int pre = c;
    #pragma unroll
    for (int o = 1; o < 32; o <<= 1) {
        int n = __shfl_up_sync(0xFFFFFFFFu, pre, o);
        if (lane >= o) pre += n;
    }
    if (lane == 31) s_wtot[wid] = pre;
    __syncthreads();
    int wbase = 0, P = 0;
    #pragma unroll
    for (int w = 0; w < NWARP; w++) {
        wbase += (w < wid) ? s_wtot[w] : 0;
        P += s_wtot[w];
    }
    int ofs = wbase + pre - c;
    #pragma unroll
    for (int a = 0; a < APT; a++) {
        if (pos[a]) {
            s_pos_row[ofs] = base + a;
            s_pos_tgt[ofs] = bidx[a];
            s_pos_lab[ofs] = s_lab[bidx[a]];
            ofs++;
        }
    }
    __syncthreads();

    // ── GIoU for positives, strided (deterministic) ──
    float bbox = 0.0f;
    for (int i = tid; i < P; i += THREADS) {
        float4 pb = ((const float4*)boxes)[s_pos_row[i]];   // L1-hot
        float plox = pb.x - 0.5f * pb.z, ploy = pb.y - 0.5f * pb.w;
        float phix = pb.x + 0.5f * pb.z, phiy = pb.y + 0.5f * pb.w;
        float pa   = pb.z * pb.w;
        int   bm   = s_pos_tgt[i];
        float4 t = s_lohi[bm];
        float wx = fmaxf(fminf(phix, t.z) - fmaxf(plox, t.x), 0.0f);
        float wy = fmaxf(fminf(phiy, t.w) - fmaxf(ploy, t.y), 0.0f);
        float inter = wx * wy;
        float uni = pa + s_area[bm] - inter;
        float iou = __fdividef(inter, uni + 1e-6f);
        float ex = fmaxf(fmaxf(phix, t.z) - fminf(plox, t.x), 0.0f);
        float ey = fmaxf(fmaxf(phiy, t.w) - fminf(ploy, t.y), 0.0f);
        float enc = ex * ey;
        bbox += 1.0f - (iou - __fdividef(enc - uni, enc + 1e-6f));
    }

    // ── focal loss over positives (P*80 items, incremental indexing) ──
    float fl = 0.0f;
    {
        const int items = P * NCLS;
        int a = 0, cc = tid;
        if (cc >= NCLS) { cc -= NCLS; a += 1; }
        for (int i = tid; i < items; i += THREADS) {
            float x = cls[s_pos_row[a] * NCLS + cc];
            bool t = (cc == s_pos_lab[a]);
            float e  = __expf(-fabsf(x));
            float q  = 1.0f + e;
            float pabs = frcp_approx(q);               // sigmoid(|x|)
            float lg = __logf(q);                      // log1p(exp(-|x|))
            float p  = (x >= 0.0f) ? pabs : 1.0f - pabs;
            float omp = t ? (1.0f - p) : p;            // 1 - p_t
            float ce = lg + fmaxf(t ? -x : x, 0.0f);
            float at = t ? 0.25f : 0.75f;
            fl += at * omp * omp * ce;
            cc += THREADS - NCLS;                      // +48
            a += 1;
            if (cc >= NCLS) { cc -= NCLS; a += 1; }
        }
    }

    // ── single-sync fused block reduction of (bce, posf, bbox, fl) ──
    float v0 = bce, v1 = posf, v2 = bbox, v3 = fl;
    #pragma unroll
    for (int off = 16; off > 0; off >>= 1) {
        v0 += __shfl_down_sync(0xFFFFFFFFu, v0, off);
        v1 += __shfl_down_sync(0xFFFFFFFFu, v1, off);
        v2 += __shfl_down_sync(0xFFFFFFFFu, v2, off);
        v3 += __shfl_down_sync(0xFFFFFFFFu, v3, off);
    }
    if (lane == 0) {
        s_red[wid][0] = v0; s_red[wid][1] = v1;
        s_red[wid][2] = v2; s_red[wid][3] = v3;
    }
    __syncthreads();
    if (tid == 0) {
        float r0 = 0, r1 = 0, r2 = 0, r3 = 0;
        #pragma unroll
        for (int w = 0; w < NWARP; w++) {
            r0 += s_red[w][0]; r1 += s_red[w][1];
            r2 += s_red[w][2]; r3 += s_red[w][3];
        }
        g_part[blockIdx.x * 4 + 0] = r0;
        g_part[blockIdx.x * 4 + 1] = r1;
        g_part[blockIdx.x * 4 + 2] = r2;
        g_part[blockIdx.x * 4 + 3] = r3;
    }

    // ── last-block finalize ──
    __threadfence();
    if (tid == 0) s_is_last = (atomicAdd(&g_count, 1) == NBLOCKS - 1) ? 1u : 0u;
    __syncthreads();
    if (!s_is_last) return;
    __threadfence();

    {
        int fimg = tid >> 4;        // 0..7 (128 threads = 8 imgs x 16 slots)
        int sub  = tid & 15;        // 0..15
        float w0 = 0, w1 = 0, w2 = 0, w3 = 0;
        for (int s = sub; s < NBLK_PER_IMG; s += 16) {
            int b = fimg * NBLK_PER_IMG + s;
            w0 += g_part[b * 4 + 0];
            w1 += g_part[b * 4 + 1];
            w2 += g_part[b * 4 + 2];
            w3 += g_part[b * 4 + 3];
        }
        #pragma unroll
        for (int off = 8; off > 0; off >>= 1) {
            w0 += __shfl_down_sync(0xFFFFFFFFu, w0, off, 16);
            w1 += __shfl_down_sync(0xFFFFFFFFu, w1, off, 16);
            w2 += __shfl_down_sync(0xFFFFFFFFu, w2, off, 16);
            w3 += __shfl_down_sync(0xFFFFFFFFu, w3, off, 16);
        }
        if (sub == 0) {
            s_img[fimg][0] = w0; s_img[fimg][1] = w1;
            s_img[fimg][2] = w2; s_img[fimg][3] = w3;
        }
        __syncthreads();
        if (tid == 0) {
            float obj_sum = 0, bbox_sum = 0, cls_sum = 0, num_pos = 0;
            #pragma unroll
            for (int i = 0; i < NIMG; i++) {
                float bces = s_img[i][0];
                float pc   = s_img[i][1];
                float bb   = s_img[i][2];
                float fls  = s_img[i][3];
                obj_sum  += bces * (1.0f * pc + 0.5f * ((float)NANCH - pc));
                bbox_sum += bb;
                cls_sum  += fls / fmaxf(pc * (float)NCLS, 1.0f);
                num_pos  += pc;
            }
            num_pos = fmaxf(num_pos, 1.0f);
            out[0] = obj_sum / (float)NIMG
                   + 5.0f * bbox_sum / num_pos
                   + cls_sum / (float)NIMG;
            g_count = 0;   // reset for next graph replay
        }
    }
}

extern "C" void kernel_launch(void* const* d_in, const int* in_sizes, int n_in,
                              void* d_out, int out_size) {
    const float* obj   = (const float*)d_in[0];
    const float* boxes = (const float*)d_in[1];
    const float* cls   = (const float*)d_in[2];
    const float* tbox  = (const float*)d_in[3];
    const int*   tlab  = (const int*)d_in[4];
    float* out = (float*)d_out;

    loss_fused<<<NBLOCKS, THREADS>>>(obj, boxes, cls, tbox, tlab, out);
}